// round 5
// baseline (speedup 1.0000x reference)
#include <cuda_runtime.h>

// BumpKNN: x [2048,16], data [65536,16] -> bump(min L2 dist) [2048]
// Strategy: fp32 packed-f32x2 FMA brute force, expansion trick matching reference.

#define THREADS   256
#define QPT       2                      // queries per thread
#define NQ        2048
#define ND        65536
#define DIMS      16
#define DSPLIT    128                    // data splits (grid.x)
#define PPC       (ND / DSPLIT)          // points per CTA = 512
#define TPTS      128                    // points staged per smem tile
#define NQTILES   (NQ / (THREADS * QPT)) // 4

// Scratch (no allocs allowed): data norms + per-split partial min dist^2
__device__ float g_d2[ND];
__device__ float g_partial[DSPLIT * NQ];

typedef unsigned long long u64;

__device__ __forceinline__ u64 pack2(float lo, float hi) {
    u64 r; asm("mov.b64 %0, {%1, %2};" : "=l"(r) : "f"(lo), "f"(hi)); return r;
}
__device__ __forceinline__ float2 unpack2(u64 v) {
    float2 r; asm("mov.b64 {%0, %1}, %2;" : "=f"(r.x), "=f"(r.y) : "l"(v)); return r;
}
__device__ __forceinline__ u64 fma2(u64 a, u64 b, u64 c) {
    u64 r; asm("fma.rn.f32x2 %0, %1, %2, %3;" : "=l"(r) : "l"(a), "l"(b), "l"(c)); return r;
}
__device__ __forceinline__ u64 add2(u64 a, u64 b) {
    u64 r; asm("add.rn.f32x2 %0, %1, %2;" : "=l"(r) : "l"(a), "l"(b)); return r;
}

// ---------------------------------------------------------------------------
// Kernel 1: data norms d2[n] = sum_d data[n][d]^2
// ---------------------------------------------------------------------------
__global__ void norm_kernel(const float* __restrict__ data) {
    int n = blockIdx.x * blockDim.x + threadIdx.x;
    const float4* p = reinterpret_cast<const float4*>(data + (size_t)n * DIMS);
    float4 a = p[0], b = p[1], c = p[2], d = p[3];
    float s = a.x * a.x + a.y * a.y + a.z * a.z + a.w * a.w
            + b.x * b.x + b.y * b.y + b.z * b.z + b.w * b.w
            + c.x * c.x + c.y * c.y + c.z * c.z + c.w * c.w
            + d.x * d.x + d.y * d.y + d.z * d.z + d.w * d.w;
    g_d2[n] = s;
}

// ---------------------------------------------------------------------------
// Kernel 2: per-(split, query) min over the split's points of (d2 - 2*x.v),
//           stored as x2 + min  (= min squared distance over the split).
// Each thread owns QPT=2 queries, holds -2*x packed as 8 f32x2 regs each.
// Accumulator initialized with {d2, 0} so lo+hi of the final packed sum is
// exactly d2 - 2*dot.
// ---------------------------------------------------------------------------
__global__ void __launch_bounds__(THREADS)
main_kernel(const float* __restrict__ x, const float* __restrict__ data) {
    __shared__ __align__(16) float sdata[TPTS][DIMS];
    __shared__ __align__(8) float2 sd2[TPTS];

    const int tid = threadIdx.x;
    const int qbase = blockIdx.y * (THREADS * QPT);
    const int q0 = qbase + tid;
    const int q1 = q0 + THREADS;

    // Load queries, compute x2, pack -2*x as f32x2 pairs.
    u64 xa[8], xb[8];
    float x2a = 0.f, x2b = 0.f;
    {
        const float4* xp = reinterpret_cast<const float4*>(x + (size_t)q0 * DIMS);
#pragma unroll
        for (int i = 0; i < 4; i++) {
            float4 v = xp[i];
            x2a += v.x * v.x + v.y * v.y + v.z * v.z + v.w * v.w;
            xa[2 * i]     = pack2(-2.f * v.x, -2.f * v.y);
            xa[2 * i + 1] = pack2(-2.f * v.z, -2.f * v.w);
        }
    }
    {
        const float4* xp = reinterpret_cast<const float4*>(x + (size_t)q1 * DIMS);
#pragma unroll
        for (int i = 0; i < 4; i++) {
            float4 v = xp[i];
            x2b += v.x * v.x + v.y * v.y + v.z * v.z + v.w * v.w;
            xb[2 * i]     = pack2(-2.f * v.x, -2.f * v.y);
            xb[2 * i + 1] = pack2(-2.f * v.z, -2.f * v.w);
        }
    }

    const u64 zz = pack2(0.f, 0.f);
    float m0 = 3.402823466e38f, m1 = 3.402823466e38f;
    const int pb0 = blockIdx.x * PPC;

    for (int it = 0; it < PPC; it += TPTS) {
        const int pb = pb0 + it;
        // Stage TPTS points (TPTS*16 floats = TPTS*4 float4) + their norms.
        {
            const float4* gp = reinterpret_cast<const float4*>(data + (size_t)pb * DIMS);
            float4* sp = reinterpret_cast<float4*>(&sdata[0][0]);
#pragma unroll
            for (int k = 0; k < (TPTS * 4) / THREADS; k++)
                sp[tid + k * THREADS] = gp[tid + k * THREADS];
            if (tid < TPTS)
                sd2[tid] = make_float2(g_d2[pb + tid], 0.f);
        }
        __syncthreads();

#pragma unroll 2
        for (int j = 0; j < TPTS; j++) {
            const ulonglong2* vp = reinterpret_cast<const ulonglong2*>(&sdata[j][0]);
            ulonglong2 v0 = vp[0], v1 = vp[1], v2 = vp[2], v3 = vp[3];
            u64 di = *reinterpret_cast<const u64*>(&sd2[j]);

            // query 0: two independent accumulation chains
            u64 a0 = fma2(xa[0], v0.x, di);
            u64 b0 = fma2(xa[1], v0.y, zz);
            // query 1
            u64 a1 = fma2(xb[0], v0.x, di);
            u64 b1 = fma2(xb[1], v0.y, zz);

            a0 = fma2(xa[2], v1.x, a0);  b0 = fma2(xa[3], v1.y, b0);
            a1 = fma2(xb[2], v1.x, a1);  b1 = fma2(xb[3], v1.y, b1);
            a0 = fma2(xa[4], v2.x, a0);  b0 = fma2(xa[5], v2.y, b0);
            a1 = fma2(xb[4], v2.x, a1);  b1 = fma2(xb[5], v2.y, b1);
            a0 = fma2(xa[6], v3.x, a0);  b0 = fma2(xa[7], v3.y, b0);
            a1 = fma2(xb[6], v3.x, a1);  b1 = fma2(xb[7], v3.y, b1);

            float2 s0 = unpack2(add2(a0, b0));
            float2 s1 = unpack2(add2(a1, b1));
            m0 = fminf(m0, s0.x + s0.y);   // = min (d2 - 2*dot)
            m1 = fminf(m1, s1.x + s1.y);
        }
        __syncthreads();
    }

    g_partial[blockIdx.x * NQ + q0] = x2a + m0;
    g_partial[blockIdx.x * NQ + q1] = x2b + m1;
}

// ---------------------------------------------------------------------------
// Kernel 3: reduce over splits + bump function (mirrors reference math)
// ---------------------------------------------------------------------------
__global__ void finalize_kernel(float* __restrict__ out) {
    int q = blockIdx.x * blockDim.x + threadIdx.x;
    float m = 3.402823466e38f;
#pragma unroll 8
    for (int s = 0; s < DSPLIT; s++)
        m = fminf(m, g_partial[s * NQ + q]);

    float nn2 = fmaxf(m, 0.0f);             // clamp tiny negatives
    float d2c = fmaxf(nn2, 1e-12f);
    float dist = sqrtf(d2c);
    float r = 0.0f;
    if (dist < 2.0f) {                       // RADIUS = 2
        float ds = dist * dist;              // match reference's sqrt->square
        r = expf(1.0f / (ds - 4.0f) + 0.25f); // DECAY/denom + DECAY/r^2
    }
    out[q] = r;
}

// ---------------------------------------------------------------------------
extern "C" void kernel_launch(void* const* d_in, const int* in_sizes, int n_in,
                              void* d_out, int out_size) {
    const float* x    = (const float*)d_in[0];
    const float* data = (const float*)d_in[1];
    // Defensive: x is 2048*16=32768 elems, data is 65536*16=1048576 elems.
    if (n_in >= 2 && in_sizes[0] > in_sizes[1]) {
        x    = (const float*)d_in[1];
        data = (const float*)d_in[0];
    }

    norm_kernel<<<ND / THREADS, THREADS>>>(data);
    dim3 grid(DSPLIT, NQTILES);
    main_kernel<<<grid, THREADS>>>(x, data);
    finalize_kernel<<<NQ / THREADS, THREADS>>>((float*)d_out);
}

// round 6
// speedup vs baseline: 1.1952x; 1.1952x over previous
#include <cuda_runtime.h>

// BumpKNN: x [2048,16], data [65536,16] -> bump(min L2 dist) [2048]
// R6: point-paired f32x2 lanes (min on alu pipe), 148-CTA single wave,
//     norm fused into staging. fma-pipe ops per query-point = 8 (floor).

#define THREADS   256
#define NQ        2048
#define ND        65536
#define DIMS      16
#define DSPLIT    37
#define PPC       1772                   // ceil(65536/37), even
#define NQTILES   4                      // 37*4 = 148 CTAs = 1/SM
#define TILE_PTS  256                    // points staged per smem tile
#define TILE_PAIR 128

__device__ float g_partial[DSPLIT * NQ];

typedef unsigned long long u64;
union U2 { u64 u; float2 f; };

__device__ __forceinline__ u64 pack2(float lo, float hi) {
    u64 r; asm("mov.b64 %0, {%1, %2};" : "=l"(r) : "f"(lo), "f"(hi)); return r;
}
__device__ __forceinline__ u64 fma2(u64 a, u64 b, u64 c) {
    u64 r; asm("fma.rn.f32x2 %0, %1, %2, %3;" : "=l"(r) : "l"(a), "l"(b), "l"(c)); return r;
}

// ---------------------------------------------------------------------------
// Main kernel: per (split, query-tile) min over split's points of
// (d2 - 2*x.v), written as x2 + min = min squared distance for the split.
// Each f32x2 lane carries a DIFFERENT data point; query dims are duplicated
// across lanes, so the running min is a per-lane FMNMX (alu pipe) and the
// fma pipe does exactly 8 FMA2 per query-point.
// ---------------------------------------------------------------------------
__global__ void __launch_bounds__(THREADS)
main_kernel(const float* __restrict__ x, const float* __restrict__ data) {
    __shared__ __align__(16) u64 spair[TILE_PAIR][DIMS]; // {pEven_d, pOdd_d}
    __shared__ __align__(8)  u64 sd2[TILE_PAIR];         // {d2Even, d2Odd}

    const int tid = threadIdx.x;
    const int q0 = blockIdx.y * (THREADS * 2) + tid;
    const int q1 = q0 + THREADS;

    // Queries: -2*x duplicated into both f32x2 lanes; x2 for the epilogue.
    u64 qa[DIMS], qb[DIMS];
    float x2a = 0.f, x2b = 0.f;
    {
        const float4* xp = reinterpret_cast<const float4*>(x + (size_t)q0 * DIMS);
#pragma unroll
        for (int i = 0; i < 4; i++) {
            float4 v = xp[i];
            x2a += v.x * v.x + v.y * v.y + v.z * v.z + v.w * v.w;
            qa[4 * i + 0] = pack2(-2.f * v.x, -2.f * v.x);
            qa[4 * i + 1] = pack2(-2.f * v.y, -2.f * v.y);
            qa[4 * i + 2] = pack2(-2.f * v.z, -2.f * v.z);
            qa[4 * i + 3] = pack2(-2.f * v.w, -2.f * v.w);
        }
    }
    {
        const float4* xp = reinterpret_cast<const float4*>(x + (size_t)q1 * DIMS);
#pragma unroll
        for (int i = 0; i < 4; i++) {
            float4 v = xp[i];
            x2b += v.x * v.x + v.y * v.y + v.z * v.z + v.w * v.w;
            qb[4 * i + 0] = pack2(-2.f * v.x, -2.f * v.x);
            qb[4 * i + 1] = pack2(-2.f * v.y, -2.f * v.y);
            qb[4 * i + 2] = pack2(-2.f * v.z, -2.f * v.z);
            qb[4 * i + 3] = pack2(-2.f * v.w, -2.f * v.w);
        }
    }

    const float INF = 3.402823466e38f;
    float mA0 = INF, mA1 = INF, mB0 = INF, mB1 = INF;

    const int pstart = blockIdx.x * PPC;
    const int pend   = (pstart + PPC < ND) ? (pstart + PPC) : ND;
    const float4* dataf4 = reinterpret_cast<const float4*>(data);

    for (int p0 = pstart; p0 < pend; p0 += TILE_PTS) {
        const int tp    = min(TILE_PTS, pend - p0);  // always even
        const int npair = tp >> 1;

        // Stage tp points into paired-dup layout (scattered STS.32).
        for (int idx = tid; idx < tp * 4; idx += THREADS) {
            const int pt = idx >> 2, i = idx & 3;     // local point, float4 idx
            float4 f = dataf4[(size_t)(p0 + pt) * 4 + i];
            const int pr = pt >> 1, half = pt & 1;
            float* bp = reinterpret_cast<float*>(&spair[pr][4 * i]) + half;
            bp[0] = f.x; bp[2] = f.y; bp[4] = f.z; bp[6] = f.w;
        }
        // d2 pair straight from global (L2-resident).
        if (tid < npair) {
            const float4* g0 = dataf4 + (size_t)(p0 + 2 * tid) * 4;
            float s0 = 0.f, s1 = 0.f;
#pragma unroll
            for (int i = 0; i < 4; i++) {
                float4 a = g0[i], b = g0[4 + i];
                s0 += a.x * a.x + a.y * a.y + a.z * a.z + a.w * a.w;
                s1 += b.x * b.x + b.y * b.y + b.z * b.z + b.w * b.w;
            }
            sd2[tid] = pack2(s0, s1);
        }
        __syncthreads();

#pragma unroll 2
        for (int j = 0; j < npair; j++) {
            const ulonglong2* vp = reinterpret_cast<const ulonglong2*>(&spair[j][0]);
            ulonglong2 w0 = vp[0], w1 = vp[1], w2 = vp[2], w3 = vp[3];
            ulonglong2 w4 = vp[4], w5 = vp[5], w6 = vp[6], w7 = vp[7];
            u64 d2j = sd2[j];

            u64 A = fma2(qa[0], w0.x, d2j);
            u64 B = fma2(qb[0], w0.x, d2j);
            A = fma2(qa[ 1], w0.y, A);  B = fma2(qb[ 1], w0.y, B);
            A = fma2(qa[ 2], w1.x, A);  B = fma2(qb[ 2], w1.x, B);
            A = fma2(qa[ 3], w1.y, A);  B = fma2(qb[ 3], w1.y, B);
            A = fma2(qa[ 4], w2.x, A);  B = fma2(qb[ 4], w2.x, B);
            A = fma2(qa[ 5], w2.y, A);  B = fma2(qb[ 5], w2.y, B);
            A = fma2(qa[ 6], w3.x, A);  B = fma2(qb[ 6], w3.x, B);
            A = fma2(qa[ 7], w3.y, A);  B = fma2(qb[ 7], w3.y, B);
            A = fma2(qa[ 8], w4.x, A);  B = fma2(qb[ 8], w4.x, B);
            A = fma2(qa[ 9], w4.y, A);  B = fma2(qb[ 9], w4.y, B);
            A = fma2(qa[10], w5.x, A);  B = fma2(qb[10], w5.x, B);
            A = fma2(qa[11], w5.y, A);  B = fma2(qb[11], w5.y, B);
            A = fma2(qa[12], w6.x, A);  B = fma2(qb[12], w6.x, B);
            A = fma2(qa[13], w6.y, A);  B = fma2(qb[13], w6.y, B);
            A = fma2(qa[14], w7.x, A);  B = fma2(qb[14], w7.x, B);
            A = fma2(qa[15], w7.y, A);  B = fma2(qb[15], w7.y, B);

            U2 ua; ua.u = A;  U2 ub; ub.u = B;
            mA0 = fminf(mA0, ua.f.x);  mA1 = fminf(mA1, ua.f.y);
            mB0 = fminf(mB0, ub.f.x);  mB1 = fminf(mB1, ub.f.y);
        }
        __syncthreads();
    }

    g_partial[blockIdx.x * NQ + q0] = x2a + fminf(mA0, mA1);
    g_partial[blockIdx.x * NQ + q1] = x2b + fminf(mB0, mB1);
}

// ---------------------------------------------------------------------------
// Finalize: min over 37 split partials + bump (mirrors reference math).
// ---------------------------------------------------------------------------
__global__ void finalize_kernel(float* __restrict__ out) {
    int q = blockIdx.x * blockDim.x + threadIdx.x;
    float m = 3.402823466e38f;
#pragma unroll
    for (int s = 0; s < DSPLIT; s++)
        m = fminf(m, g_partial[s * NQ + q]);

    float nn2  = fmaxf(m, 0.0f);              // clamp tiny negatives
    float d2c  = fmaxf(nn2, 1e-12f);
    float dist = sqrtf(d2c);
    float r = 0.0f;
    if (dist < 2.0f) {                         // RADIUS = 2
        float ds = dist * dist;                // match reference sqrt->square
        r = expf(1.0f / (ds - 4.0f) + 0.25f);  // DECAY/denom + DECAY/r^2
    }
    out[q] = r;
}

// ---------------------------------------------------------------------------
extern "C" void kernel_launch(void* const* d_in, const int* in_sizes, int n_in,
                              void* d_out, int out_size) {
    const float* x    = (const float*)d_in[0];
    const float* data = (const float*)d_in[1];
    if (n_in >= 2 && in_sizes[0] > in_sizes[1]) {  // defensive order check
        x    = (const float*)d_in[1];
        data = (const float*)d_in[0];
    }

    dim3 grid(DSPLIT, NQTILES);
    main_kernel<<<grid, THREADS>>>(x, data);
    finalize_kernel<<<NQ / THREADS, THREADS>>>((float*)d_out);
}

// round 9
// speedup vs baseline: 1.6009x; 1.3395x over previous
#include <cuda_runtime.h>
#include <cstdint>

// BumpKNN R8: 3xTF32 via legacy mma.sync.m16n8k8 (baseline PTX, no tcgen05).
// D = d2[n] (fp32 accum init) - 2*x.v (3-pass tf32 emulation); min in regs;
// x2 + bump applied in finalize.

#define NQ      2048
#define ND      65536
#define STRIPS  16          // 2048 / 128 queries per CTA
#define SPLITS  9           // 16*9 = 144 CTAs ~ one wave
#define NTILE   128         // points per smem tile
#define THREADS 256
#define KPAD    20          // floats per point row: conflict-free LDS pattern

__device__ float g_partial[SPLITS * NQ];

__device__ __forceinline__ uint32_t f2tf(float x) {
    uint32_t r; asm("cvt.rna.tf32.f32 %0, %1;" : "=r"(r) : "f"(x)); return r;
}

__device__ __forceinline__ void mma8(float c[4],
                                     uint32_t a0, uint32_t a1, uint32_t a2, uint32_t a3,
                                     uint32_t b0, uint32_t b1) {
    asm("mma.sync.aligned.m16n8k8.row.col.f32.tf32.tf32.f32 "
        "{%0,%1,%2,%3}, {%4,%5,%6,%7}, {%8,%9}, {%0,%1,%2,%3};"
        : "+f"(c[0]), "+f"(c[1]), "+f"(c[2]), "+f"(c[3])
        : "r"(a0), "r"(a1), "r"(a2), "r"(a3), "r"(b0), "r"(b1));
}

// ---------------------------------------------------------------------------
__global__ void __launch_bounds__(THREADS, 1)
mma_kernel(const float* __restrict__ x, const float* __restrict__ data) {
    __shared__ __align__(16) float sBhi[2][NTILE][KPAD];
    __shared__ __align__(16) float sBlo[2][NTILE][KPAD];
    __shared__ __align__(8)  float sD2[2][NTILE];

    const int tid = threadIdx.x, lane = tid & 31, w = tid >> 5;
    const int strip = blockIdx.x, split = blockIdx.y;
    const int tiles = (split < 8) ? 57 : 56;       // 8*57 + 56 = 512 tiles
    const int tbase = split * 57;

    const int g4 = lane >> 2, kc = lane & 3;
    const int qb = strip * 128 + w * 16;           // 16 query rows per warp

    // A fragments: -2*x, tf32 hi/lo, for 2 k-chunks (K=16).
    // a0:(row0,k), a1:(row1,k), a2:(row0,k+4), a3:(row1,k+4); rowX = g4 (+8).
    uint32_t ah[2][4], al[2][4];
#pragma unroll
    for (int c = 0; c < 2; c++)
#pragma unroll
        for (int j = 0; j < 4; j++) {
            int row = g4 + (j & 1) * 8;
            int k   = c * 8 + kc + (j >> 1) * 4;
            float s = -2.f * __ldg(&x[(size_t)(qb + row) * 16 + k]);
            uint32_t h = f2tf(s);
            ah[c][j] = h;
            al[c][j] = f2tf(s - __uint_as_float(h));
        }

    const float4* dv = reinterpret_cast<const float4*>(data);
    const bool loader = tid < NTILE;
    float4 r0, r1, r2, r3;

    // Convert prefetched point -> hi/lo tf32 rows + d2 into buffer `buf`.
    auto stash = [&](int buf) {
        float v[16] = {r0.x, r0.y, r0.z, r0.w, r1.x, r1.y, r1.z, r1.w,
                       r2.x, r2.y, r2.z, r2.w, r3.x, r3.y, r3.z, r3.w};
        float d2 = 0.f;
        uint32_t hi[16], lo[16];
#pragma unroll
        for (int i = 0; i < 16; i++) {
            d2 = fmaf(v[i], v[i], d2);
            hi[i] = f2tf(v[i]);
            lo[i] = f2tf(v[i] - __uint_as_float(hi[i]));
        }
        uint4* ph = reinterpret_cast<uint4*>(&sBhi[buf][tid][0]);
        uint4* pl = reinterpret_cast<uint4*>(&sBlo[buf][tid][0]);
#pragma unroll
        for (int b = 0; b < 4; b++) {
            ph[b] = make_uint4(hi[4*b], hi[4*b+1], hi[4*b+2], hi[4*b+3]);
            pl[b] = make_uint4(lo[4*b], lo[4*b+1], lo[4*b+2], lo[4*b+3]);
        }
        sD2[buf][tid] = d2;
    };

    // Prologue: tile 0.
    if (loader) {
        size_t p = (size_t)tbase * NTILE + tid;
        r0 = dv[p*4+0]; r1 = dv[p*4+1]; r2 = dv[p*4+2]; r3 = dv[p*4+3];
        stash(0);
    }
    __syncthreads();

    const float INF = 3.402823466e38f;
    float m0 = INF, m1 = INF, m2 = INF, m3 = INF;

    for (int t = 0; t < tiles; t++) {
        const int buf = t & 1;
        if (t + 1 < tiles && loader) {            // prefetch next tile
            size_t p = (size_t)(tbase + t + 1) * NTILE + tid;
            r0 = dv[p*4+0]; r1 = dv[p*4+1]; r2 = dv[p*4+2]; r3 = dv[p*4+3];
        }

        const float* bh_ = &sBhi[buf][0][0];
        const float* bl_ = &sBlo[buf][0][0];
        const float* d2_ = &sD2[buf][0];
#pragma unroll
        for (int it = 0; it < NTILE / 8; it++) {   // 16 n8 groups
            const int nb = it * 8;
            const uint32_t* rh = reinterpret_cast<const uint32_t*>(bh_ + (nb + g4) * KPAD);
            const uint32_t* rl = reinterpret_cast<const uint32_t*>(bl_ + (nb + g4) * KPAD);
            uint32_t bh0 = rh[kc],     bh1 = rh[kc + 4];
            uint32_t bh2 = rh[kc + 8], bh3 = rh[kc + 12];
            uint32_t bl0 = rl[kc],     bl1 = rl[kc + 4];
            uint32_t bl2 = rl[kc + 8], bl3 = rl[kc + 12];

            float2 dd = *reinterpret_cast<const float2*>(d2_ + nb + 2 * kc);
            float c[4] = {dd.x, dd.y, dd.x, dd.y};  // accum init = d2[col]

            mma8(c, ah[0][0], ah[0][1], ah[0][2], ah[0][3], bh0, bh1); // hh k0
            mma8(c, ah[1][0], ah[1][1], ah[1][2], ah[1][3], bh2, bh3); // hh k1
            mma8(c, ah[0][0], ah[0][1], ah[0][2], ah[0][3], bl0, bl1); // hl k0
            mma8(c, ah[1][0], ah[1][1], ah[1][2], ah[1][3], bl2, bl3); // hl k1
            mma8(c, al[0][0], al[0][1], al[0][2], al[0][3], bh0, bh1); // lh k0
            mma8(c, al[1][0], al[1][1], al[1][2], al[1][3], bh2, bh3); // lh k1

            m0 = fminf(m0, c[0]); m1 = fminf(m1, c[1]);
            m2 = fminf(m2, c[2]); m3 = fminf(m3, c[3]);
        }

        if (t + 1 < tiles && loader) stash((t + 1) & 1);
        __syncthreads();
    }

    // Row mins: c0/c1 -> row g4, c2/c3 -> row g4+8; reduce across the 4 lanes
    // sharing a row (lane bits 0-1).
    float rA = fminf(m0, m1);
    float rB = fminf(m2, m3);
    rA = fminf(rA, __shfl_xor_sync(0xffffffffu, rA, 1));
    rA = fminf(rA, __shfl_xor_sync(0xffffffffu, rA, 2));
    rB = fminf(rB, __shfl_xor_sync(0xffffffffu, rB, 1));
    rB = fminf(rB, __shfl_xor_sync(0xffffffffu, rB, 2));
    if (kc == 0) {
        g_partial[split * NQ + qb + g4]     = rA;  // = min(d2 - 2*dot)
        g_partial[split * NQ + qb + g4 + 8] = rB;
    }
}

// ---------------------------------------------------------------------------
// Finalize: add x2, min over splits, bump (mirrors reference math).
// ---------------------------------------------------------------------------
__global__ void finalize_kernel(const float* __restrict__ x, float* __restrict__ out) {
    int q = blockIdx.x * blockDim.x + threadIdx.x;
    const float4* xp = reinterpret_cast<const float4*>(x + (size_t)q * 16);
    float4 a = xp[0], b = xp[1], c = xp[2], d = xp[3];
    float x2 = a.x*a.x + a.y*a.y + a.z*a.z + a.w*a.w
             + b.x*b.x + b.y*b.y + b.z*b.z + b.w*b.w
             + c.x*c.x + c.y*c.y + c.z*c.z + c.w*c.w
             + d.x*d.x + d.y*d.y + d.z*d.z + d.w*d.w;

    float m = 3.402823466e38f;
#pragma unroll
    for (int s = 0; s < SPLITS; s++)
        m = fminf(m, g_partial[s * NQ + q]);

    float nn2  = fmaxf(x2 + m, 0.0f);           // clamp tiny negatives
    float d2c  = fmaxf(nn2, 1e-12f);
    float dist = sqrtf(d2c);
    float r = 0.0f;
    if (dist < 2.0f) {                           // RADIUS = 2
        float ds = dist * dist;                  // match reference sqrt->square
        r = expf(1.0f / (ds - 4.0f) + 0.25f);    // DECAY/denom + DECAY/r^2
    }
    out[q] = r;
}

// ---------------------------------------------------------------------------
extern "C" void kernel_launch(void* const* d_in, const int* in_sizes, int n_in,
                              void* d_out, int out_size) {
    const float* x    = (const float*)d_in[0];
    const float* data = (const float*)d_in[1];
    if (n_in >= 2 && in_sizes[0] > in_sizes[1]) {  // defensive order check
        x    = (const float*)d_in[1];
        data = (const float*)d_in[0];
    }

    dim3 grid(STRIPS, SPLITS);
    mma_kernel<<<grid, THREADS>>>(x, data);
    finalize_kernel<<<NQ / THREADS, THREADS>>>(x, (float*)d_out);
}